// round 1
// baseline (speedup 1.0000x reference)
#include <cuda_runtime.h>
#include <cstdint>
#include <cstddef>

// ---------------- problem constants ----------------
#define DIMD   2048
#define BATCH  4
#define SEQ    4096
#define MTOT   (BATCH*SEQ)      // 16384 rows (tokens)
#define N1     (3*DIMD)         // 6144
#define KD     DIMD             // 2048 (GEMM K)

// ---------------- scratch (no cudaMalloc allowed -> __device__ globals) ----
__device__ float g_xn[(size_t)MTOT * KD];        // rmsnorm(x), tf32-rounded
__device__ float g_h [(size_t)MTOT * N1];        // expand output
__device__ float g_o [(size_t)MTOT * KD];        // gated conv output, tf32-rounded
__device__ float g_We[(size_t)N1  * KD];         // tf32-rounded W_expand
__device__ float g_Wp[(size_t)KD  * KD];         // tf32-rounded W_proj

// ---------------- helpers ----------------
__device__ __forceinline__ float to_tf32(float x) {
    float r;
    asm("cvt.rna.tf32.f32 %0, %1;" : "=f"(r) : "f"(x));
    return r;
}

__device__ __forceinline__ void cpasync16(void* smem, const void* gmem) {
    uint32_t s = (uint32_t)__cvta_generic_to_shared(smem);
    asm volatile("cp.async.cg.shared.global [%0], [%1], 16;" :: "r"(s), "l"(gmem));
}
#define CP_COMMIT() asm volatile("cp.async.commit_group;")
#define CP_WAIT0()  asm volatile("cp.async.wait_group 0;")

__device__ __forceinline__ void mma_tf32(float c[4], const uint32_t a[4], const uint32_t b[2]) {
    asm volatile(
        "mma.sync.aligned.m16n8k8.row.col.f32.tf32.tf32.f32 "
        "{%0,%1,%2,%3}, {%4,%5,%6,%7}, {%8,%9}, {%0,%1,%2,%3};"
        : "+f"(c[0]), "+f"(c[1]), "+f"(c[2]), "+f"(c[3])
        : "r"(a[0]), "r"(a[1]), "r"(a[2]), "r"(a[3]),
          "r"(b[0]), "r"(b[1]));
}

// ---------------- prep: round weights to tf32 (RNA) ----------------
__global__ void round_We_k(const float* __restrict__ src) {
    size_t i = (size_t)blockIdx.x * blockDim.x + threadIdx.x;
    size_t n4 = (size_t)N1 * KD / 4;
    if (i >= n4) return;
    float4 v = ((const float4*)src)[i];
    v.x = to_tf32(v.x); v.y = to_tf32(v.y); v.z = to_tf32(v.z); v.w = to_tf32(v.w);
    ((float4*)g_We)[i] = v;
}
__global__ void round_Wp_k(const float* __restrict__ src) {
    size_t i = (size_t)blockIdx.x * blockDim.x + threadIdx.x;
    size_t n4 = (size_t)KD * KD / 4;
    if (i >= n4) return;
    float4 v = ((const float4*)src)[i];
    v.x = to_tf32(v.x); v.y = to_tf32(v.y); v.z = to_tf32(v.z); v.w = to_tf32(v.w);
    ((float4*)g_Wp)[i] = v;
}

// ---------------- rmsnorm: one block per token row ----------------
__global__ void __launch_bounds__(256) rmsnorm_k(const float* __restrict__ x) {
    int row = blockIdx.x;
    const float4* xr = (const float4*)(x + (size_t)row * DIMD);
    float4* outr = (float4*)(g_xn + (size_t)row * DIMD);
    int t = threadIdx.x;

    float4 a = xr[t];
    float4 b = xr[t + 256];
    float ss = a.x*a.x + a.y*a.y + a.z*a.z + a.w*a.w
             + b.x*b.x + b.y*b.y + b.z*b.z + b.w*b.w;

    // warp reduce
    #pragma unroll
    for (int off = 16; off > 0; off >>= 1)
        ss += __shfl_xor_sync(0xffffffffu, ss, off);

    __shared__ float red[8];
    __shared__ float sscale;
    int warp = t >> 5, lane = t & 31;
    if (lane == 0) red[warp] = ss;
    __syncthreads();
    if (t == 0) {
        float tot = 0.f;
        #pragma unroll
        for (int i = 0; i < 8; i++) tot += red[i];
        sscale = rsqrtf(tot * (1.0f / DIMD) + 1.1920928955078125e-07f);
    }
    __syncthreads();
    float sc = sscale;

    a.x = to_tf32(a.x * sc); a.y = to_tf32(a.y * sc); a.z = to_tf32(a.z * sc); a.w = to_tf32(a.w * sc);
    b.x = to_tf32(b.x * sc); b.y = to_tf32(b.y * sc); b.z = to_tf32(b.z * sc); b.w = to_tf32(b.w * sc);
    outr[t] = a;
    outr[t + 256] = b;
}

// ---------------- tiled tf32 GEMM: C[M,N] = A[M,K] * B[N,K]^T ----------------
// BM=BN=128, BK=16, 256 threads (8 warps as 2(M) x 4(N), warp tile 64x32)
constexpr int BM = 128, BN = 128, BK = 16;

template<int N, bool FUSE>
__global__ void __launch_bounds__(256) gemm_k(const float* __restrict__ A,
                                              const float* __restrict__ B,
                                              float* __restrict__ C,
                                              const float* __restrict__ xres,
                                              const float* __restrict__ cs) {
    constexpr int K = KD;
    __shared__ float sA[2][BM][BK + 4];
    __shared__ float sB[2][BN][BK + 4];

    const int bm = blockIdx.y * BM;
    const int bn = blockIdx.x * BN;
    const int tid  = threadIdx.x;
    const int warp = tid >> 5, lane = tid & 31;
    const int wm = (warp & 1) * 64;
    const int wn = (warp >> 1) * 32;
    const int gid = lane >> 2, tig = lane & 3;

    float acc[4][4][4];
    #pragma unroll
    for (int mi = 0; mi < 4; mi++)
        #pragma unroll
        for (int ni = 0; ni < 4; ni++)
            #pragma unroll
            for (int r = 0; r < 4; r++) acc[mi][ni][r] = 0.f;

    auto load_tile = [&](int kt, int buf) {
        int k0 = kt * BK;
        #pragma unroll
        for (int i = 0; i < 2; i++) {
            int c = tid + i * 256;          // 0..511 -> 128 rows x 4 chunks
            int row = c >> 2;
            int kk = (c & 3) * 4;
            cpasync16(&sA[buf][row][kk], A + (size_t)(bm + row) * K + k0 + kk);
            cpasync16(&sB[buf][row][kk], B + (size_t)(bn + row) * K + k0 + kk);
        }
    };

    load_tile(0, 0);
    CP_COMMIT();
    CP_WAIT0();
    __syncthreads();

    constexpr int KT = K / BK;  // 128
    for (int kt = 0; kt < KT; kt++) {
        int cur = kt & 1;
        if (kt + 1 < KT) { load_tile(kt + 1, cur ^ 1); CP_COMMIT(); }

        #pragma unroll
        for (int ks = 0; ks < 2; ks++) {
            uint32_t af[4][4], bf[4][2];
            #pragma unroll
            for (int mi = 0; mi < 4; mi++) {
                int r = wm + mi * 16 + gid;
                af[mi][0] = __float_as_uint(sA[cur][r    ][ks*8 + tig    ]);
                af[mi][1] = __float_as_uint(sA[cur][r + 8][ks*8 + tig    ]);
                af[mi][2] = __float_as_uint(sA[cur][r    ][ks*8 + tig + 4]);
                af[mi][3] = __float_as_uint(sA[cur][r + 8][ks*8 + tig + 4]);
            }
            #pragma unroll
            for (int ni = 0; ni < 4; ni++) {
                int cn = wn + ni * 8 + gid;
                bf[ni][0] = __float_as_uint(sB[cur][cn][ks*8 + tig    ]);
                bf[ni][1] = __float_as_uint(sB[cur][cn][ks*8 + tig + 4]);
            }
            #pragma unroll
            for (int mi = 0; mi < 4; mi++)
                #pragma unroll
                for (int ni = 0; ni < 4; ni++)
                    mma_tf32(acc[mi][ni], af[mi], bf[ni]);
        }

        CP_WAIT0();
        __syncthreads();
    }

    // epilogue (optionally fused residual: out = x + cs[n]*acc)
    #pragma unroll
    for (int mi = 0; mi < 4; mi++) {
        #pragma unroll
        for (int ni = 0; ni < 4; ni++) {
            int r0 = bm + wm + mi * 16 + gid;
            int c0 = bn + wn + ni * 8 + tig * 2;
            #pragma unroll
            for (int h = 0; h < 2; h++) {
                int r = r0 + h * 8;
                size_t off = (size_t)r * N + c0;
                float v0 = acc[mi][ni][2*h + 0];
                float v1 = acc[mi][ni][2*h + 1];
                if (FUSE) {
                    v0 = xres[off]     + cs[c0]     * v0;
                    v1 = xres[off + 1] + cs[c0 + 1] * v1;
                }
                float2 st; st.x = v0; st.y = v1;
                *(float2*)(C + off) = st;
            }
        }
    }
}

// ---------------- gate * causal dwconv * gate ----------------
// h layout per row: [B_gate(0:2048) | C_gate(2048:4096) | z(4096:6144)]
// y[s] = B[s]*z[s];  conv[s] = w0*y[s-2d] + w1*y[s-d] + w2*y[s] + bias
// o[s] = C[s] * conv[s]   (tf32-rounded for GEMM2)
__global__ void __launch_bounds__(256) gateconv_k(const float* __restrict__ cw,
                                                  const float* __restrict__ cb,
                                                  const int* __restrict__ dil_p) {
    int dil = *dil_p;
    size_t idx = (size_t)blockIdx.x * blockDim.x + threadIdx.x;
    if (idx >= (size_t)MTOT * DIMD) return;
    int d = (int)(idx % DIMD);
    int m = (int)(idx / DIMD);
    int s = m % SEQ;

    const float* hr = g_h + (size_t)m * N1;
    float w0 = cw[d * 3 + 0], w1 = cw[d * 3 + 1], w2 = cw[d * 3 + 2];

    float acc = cb[d];
    acc += w2 * (hr[d] * hr[2 * DIMD + d]);                     // y[s]
    if (s >= dil) {
        const float* hp = hr - (size_t)dil * N1;
        acc += w1 * (hp[d] * hp[2 * DIMD + d]);                 // y[s-d]
    }
    if (s >= 2 * dil) {
        const float* hp = hr - (size_t)(2 * dil) * N1;
        acc += w0 * (hp[d] * hp[2 * DIMD + d]);                 // y[s-2d]
    }
    float Cg = hr[DIMD + d];
    g_o[idx] = to_tf32(Cg * acc);
}

// ---------------- launch ----------------
extern "C" void kernel_launch(void* const* d_in, const int* in_sizes, int n_in,
                              void* d_out, int out_size) {
    const float* x   = (const float*)d_in[0];
    const float* We  = (const float*)d_in[1];
    const float* cw  = (const float*)d_in[2];
    const float* cb  = (const float*)d_in[3];
    const float* Wp  = (const float*)d_in[4];
    const float* cs  = (const float*)d_in[5];
    const int*   dil = (const int*)  d_in[6];

    float* out = (float*)d_out;

    // resolve device addresses of __device__ scratch
    float *p_xn, *p_h, *p_o, *p_We, *p_Wp;
    cudaGetSymbolAddress((void**)&p_xn, g_xn);
    cudaGetSymbolAddress((void**)&p_h,  g_h);
    cudaGetSymbolAddress((void**)&p_o,  g_o);
    cudaGetSymbolAddress((void**)&p_We, g_We);
    cudaGetSymbolAddress((void**)&p_Wp, g_Wp);

    // 1) pre-round weights to tf32 (RNA)
    {
        size_t n4 = (size_t)N1 * KD / 4;
        round_We_k<<<(unsigned)((n4 + 255) / 256), 256>>>(We);
        n4 = (size_t)KD * KD / 4;
        round_Wp_k<<<(unsigned)((n4 + 255) / 256), 256>>>(Wp);
    }

    // 2) rmsnorm (tf32-rounded output)
    rmsnorm_k<<<MTOT, 256>>>(x);

    // 3) expand GEMM: h = xn @ We^T   [16384 x 6144]
    gemm_k<N1, false><<<dim3(N1 / BN, MTOT / BM), 256>>>(p_xn, p_We, p_h, nullptr, nullptr);

    // 4) gate * causal conv * gate
    {
        size_t n = (size_t)MTOT * DIMD;
        gateconv_k<<<(unsigned)((n + 255) / 256), 256>>>(cw, cb, dil);
    }

    // 5) proj GEMM fused with residual: out = x + cs * (o @ Wp^T)
    gemm_k<KD, true><<<dim3(KD / BN, MTOT / BM), 256>>>(p_o, p_Wp, out, x, cs);
}

// round 3
// speedup vs baseline: 1.1232x; 1.1232x over previous
#include <cuda_runtime.h>
#include <cstdint>
#include <cstddef>

// ---------------- problem constants ----------------
#define DIMD   2048
#define MTOT   16384            // 4*4096 tokens
#define N1     6144             // 3*DIMD
#define KD     2048
#define SEQ    4096

// ---------------- scratch ----------------
__device__ float g_xn[(size_t)MTOT * KD];
__device__ float g_h [(size_t)MTOT * N1];
__device__ float g_o [(size_t)MTOT * KD];
__device__ float g_We[(size_t)N1  * KD];
__device__ float g_Wp[(size_t)KD  * KD];

// ---------------- helpers ----------------
__device__ __forceinline__ float to_tf32(float x) {
    float r; asm("cvt.rna.tf32.f32 %0, %1;" : "=f"(r) : "f"(x)); return r;
}
__device__ __forceinline__ void cpasync16(void* smem, const void* gmem) {
    uint32_t s = (uint32_t)__cvta_generic_to_shared(smem);
    asm volatile("cp.async.cg.shared.global [%0], [%1], 16;" :: "r"(s), "l"(gmem));
}
#define CP_COMMIT() asm volatile("cp.async.commit_group;")
#define CP_WAIT1()  asm volatile("cp.async.wait_group 1;")

__device__ __forceinline__ void mma_tf32(float c[4], const uint32_t a[4], const uint32_t b[2]) {
    asm volatile(
        "mma.sync.aligned.m16n8k8.row.col.f32.tf32.tf32.f32 "
        "{%0,%1,%2,%3}, {%4,%5,%6,%7}, {%8,%9}, {%0,%1,%2,%3};"
        : "+f"(c[0]), "+f"(c[1]), "+f"(c[2]), "+f"(c[3])
        : "r"(a[0]), "r"(a[1]), "r"(a[2]), "r"(a[3]),
          "r"(b[0]), "r"(b[1]));
}

// ---------------- tf32 GEMM v3: C[M,N] = A[M,K] * B[N,K]^T ----------------
// CTA tile 128x256, 8 warps (2M x 4N), warp tile 64x64 (mi=4, ni=8)
// BK=16 (2 ks-steps of k8), 3-stage cp.async pipeline, register-double-buffered
// fragments so MMAs never wait on LDS latency.
constexpr int BM = 128, BN = 256, BK = 16, NSTG = 3;
constexpr int LDS_STRIDE = BK + 4;                   // 20 floats
constexpr int A_FLOATS = BM * LDS_STRIDE;            // 2560
constexpr int B_FLOATS = BN * LDS_STRIDE;            // 5120
constexpr int STG_FLOATS = A_FLOATS + B_FLOATS;      // 7680
constexpr int SMEM_SZ = NSTG * STG_FLOATS * 4;       // 92160 B

template<int N, bool FUSE>
__global__ void __launch_bounds__(256, 1) gemm_k(const float* __restrict__ A,
                                                 const float* __restrict__ B,
                                                 float* __restrict__ C,
                                                 const float* __restrict__ xres,
                                                 const float* __restrict__ cs) {
    constexpr int K = KD;
    constexpr int KT = K / BK;    // 128
    extern __shared__ float smem[];

    const int bm = blockIdx.y * BM;
    const int bn = blockIdx.x * BN;
    const int tid  = threadIdx.x;
    const int warp = tid >> 5, lane = tid & 31;
    const int wm = (warp & 1) * 64;         // warp M offset
    const int wn = (warp >> 1) * 64;        // warp N offset
    const int gid = lane >> 2, tig = lane & 3;

    float acc[4][8][4];
    #pragma unroll
    for (int mi = 0; mi < 4; mi++)
        #pragma unroll
        for (int ni = 0; ni < 8; ni++)
            #pragma unroll
            for (int r = 0; r < 4; r++) acc[mi][ni][r] = 0.f;

    const float* Abase = A + (size_t)bm * K;
    const float* Bbase = B + (size_t)bn * K;

    auto load_stage = [&](int kt) {
        float* sa = smem + (kt % NSTG) * STG_FLOATS;
        float* sb = sa + A_FLOATS;
        const float* Ag = Abase + kt * BK;
        const float* Bg = Bbase + kt * BK;
        // A: 128 rows x 4 chunks(16B) = 512, 2 per thread
        #pragma unroll
        for (int i = 0; i < 2; i++) {
            int c = tid + i * 256;
            int row = c >> 2, ck = c & 3;
            cpasync16(sa + row * LDS_STRIDE + ck * 4, Ag + (size_t)row * K + ck * 4);
        }
        // B: 256 rows x 4 chunks = 1024, 4 per thread
        #pragma unroll
        for (int i = 0; i < 4; i++) {
            int c = tid + i * 256;
            int row = c >> 2, ck = c & 3;
            cpasync16(sb + row * LDS_STRIDE + ck * 4, Bg + (size_t)row * K + ck * 4);
        }
    };

    uint32_t fa[2][4][4];
    uint32_t fb[2][8][2];

    auto load_frags = [&](int buf, int stage, int ks) {
        const float* sa = smem + stage * STG_FLOATS;
        const float* sb = sa + A_FLOATS;
        const int k0 = ks * 8;
        #pragma unroll
        for (int mi = 0; mi < 4; mi++) {
            const float* p = sa + (wm + mi * 16 + gid) * LDS_STRIDE + k0;
            fa[buf][mi][0] = __float_as_uint(p[tig]);
            fa[buf][mi][1] = __float_as_uint(p[8 * LDS_STRIDE + tig]);
            fa[buf][mi][2] = __float_as_uint(p[tig + 4]);
            fa[buf][mi][3] = __float_as_uint(p[8 * LDS_STRIDE + tig + 4]);
        }
        #pragma unroll
        for (int ni = 0; ni < 8; ni++) {
            const float* p = sb + (wn + ni * 8 + gid) * LDS_STRIDE + k0;
            fb[buf][ni][0] = __float_as_uint(p[tig]);
            fb[buf][ni][1] = __float_as_uint(p[tig + 4]);
        }
    };

    auto mma_all = [&](int buf) {
        #pragma unroll
        for (int mi = 0; mi < 4; mi++)
            #pragma unroll
            for (int ni = 0; ni < 8; ni++)
                mma_tf32(acc[mi][ni], fa[buf][mi], fb[buf][ni]);
    };

    // prologue: 2 stages in flight
    load_stage(0); CP_COMMIT();
    load_stage(1); CP_COMMIT();
    CP_WAIT1();               // stage 0 ready
    __syncthreads();
    load_frags(0, 0, 0);

    #pragma unroll 1
    for (int kt = 0; kt < KT; kt++) {
        const int stage = kt % NSTG;
        // ---- ks = 0 ----
        load_frags(1, stage, 1);            // prefetch ks=1 frags
        if (kt + 2 < KT) load_stage(kt + 2);
        CP_COMMIT();
        mma_all(0);
        // ---- ks = 1 ----
        if (kt + 1 < KT) {
            CP_WAIT1();                     // stage kt+1 ready
            __syncthreads();
            load_frags(0, (kt + 1) % NSTG, 0);  // prefetch next tile ks=0
        }
        mma_all(1);
    }

    // epilogue
    #pragma unroll
    for (int mi = 0; mi < 4; mi++) {
        #pragma unroll
        for (int ni = 0; ni < 8; ni++) {
            int r0 = bm + wm + mi * 16 + gid;
            int c0 = bn + wn + ni * 8 + tig * 2;
            #pragma unroll
            for (int h = 0; h < 2; h++) {
                int r = r0 + h * 8;
                size_t off = (size_t)r * N + c0;
                float v0 = acc[mi][ni][2 * h + 0];
                float v1 = acc[mi][ni][2 * h + 1];
                if (FUSE) {
                    v0 = xres[off]     + cs[c0]     * v0;
                    v1 = xres[off + 1] + cs[c0 + 1] * v1;
                }
                float2 st; st.x = v0; st.y = v1;
                *(float2*)(C + off) = st;
            }
        }
    }
}

// ---------------- prep: round weights to tf32 (RNA) ----------------
__global__ void round_We_k(const float* __restrict__ src) {
    size_t i = (size_t)blockIdx.x * blockDim.x + threadIdx.x;
    size_t n4 = (size_t)N1 * KD / 4;
    if (i >= n4) return;
    float4 v = ((const float4*)src)[i];
    v.x = to_tf32(v.x); v.y = to_tf32(v.y); v.z = to_tf32(v.z); v.w = to_tf32(v.w);
    ((float4*)g_We)[i] = v;
}
__global__ void round_Wp_k(const float* __restrict__ src) {
    size_t i = (size_t)blockIdx.x * blockDim.x + threadIdx.x;
    size_t n4 = (size_t)KD * KD / 4;
    if (i >= n4) return;
    float4 v = ((const float4*)src)[i];
    v.x = to_tf32(v.x); v.y = to_tf32(v.y); v.z = to_tf32(v.z); v.w = to_tf32(v.w);
    ((float4*)g_Wp)[i] = v;
}

// ---------------- rmsnorm ----------------
__global__ void __launch_bounds__(256) rmsnorm_k(const float* __restrict__ x) {
    int row = blockIdx.x;
    const float4* xr = (const float4*)(x + (size_t)row * DIMD);
    float4* outr = (float4*)(g_xn + (size_t)row * DIMD);
    int t = threadIdx.x;

    float4 a = xr[t];
    float4 b = xr[t + 256];
    float ss = a.x*a.x + a.y*a.y + a.z*a.z + a.w*a.w
             + b.x*b.x + b.y*b.y + b.z*b.z + b.w*b.w;
    #pragma unroll
    for (int off = 16; off > 0; off >>= 1)
        ss += __shfl_xor_sync(0xffffffffu, ss, off);

    __shared__ float red[8];
    __shared__ float sscale;
    int warp = t >> 5, lane = t & 31;
    if (lane == 0) red[warp] = ss;
    __syncthreads();
    if (t == 0) {
        float tot = 0.f;
        #pragma unroll
        for (int i = 0; i < 8; i++) tot += red[i];
        sscale = rsqrtf(tot * (1.0f / DIMD) + 1.1920928955078125e-07f);
    }
    __syncthreads();
    float sc = sscale;
    a.x = to_tf32(a.x * sc); a.y = to_tf32(a.y * sc); a.z = to_tf32(a.z * sc); a.w = to_tf32(a.w * sc);
    b.x = to_tf32(b.x * sc); b.y = to_tf32(b.y * sc); b.z = to_tf32(b.z * sc); b.w = to_tf32(b.w * sc);
    outr[t] = a;
    outr[t + 256] = b;
}

// ---------------- gate * causal dwconv * gate ----------------
__global__ void __launch_bounds__(256) gateconv_k(const float* __restrict__ cw,
                                                  const float* __restrict__ cb,
                                                  const int* __restrict__ dil_p) {
    int dil = *dil_p;
    size_t idx = (size_t)blockIdx.x * blockDim.x + threadIdx.x;
    if (idx >= (size_t)MTOT * DIMD) return;
    int d = (int)(idx % DIMD);
    int m = (int)(idx / DIMD);
    int s = m % SEQ;

    const float* hr = g_h + (size_t)m * N1;
    float w0 = cw[d * 3 + 0], w1 = cw[d * 3 + 1], w2 = cw[d * 3 + 2];

    float acc = cb[d];
    acc += w2 * (hr[d] * hr[2 * DIMD + d]);
    if (s >= dil) {
        const float* hp = hr - (size_t)dil * N1;
        acc += w1 * (hp[d] * hp[2 * DIMD + d]);
    }
    if (s >= 2 * dil) {
        const float* hp = hr - (size_t)(2 * dil) * N1;
        acc += w0 * (hp[d] * hp[2 * DIMD + d]);
    }
    float Cg = hr[DIMD + d];
    g_o[idx] = to_tf32(Cg * acc);
}

// ---------------- launch ----------------
extern "C" void kernel_launch(void* const* d_in, const int* in_sizes, int n_in,
                              void* d_out, int out_size) {
    const float* x   = (const float*)d_in[0];
    const float* We  = (const float*)d_in[1];
    const float* cw  = (const float*)d_in[2];
    const float* cb  = (const float*)d_in[3];
    const float* Wp  = (const float*)d_in[4];
    const float* cs  = (const float*)d_in[5];
    const int*   dil = (const int*)  d_in[6];
    float* out = (float*)d_out;

    float *p_xn, *p_h, *p_o, *p_We, *p_Wp;
    cudaGetSymbolAddress((void**)&p_xn, g_xn);
    cudaGetSymbolAddress((void**)&p_h,  g_h);
    cudaGetSymbolAddress((void**)&p_o,  g_o);
    cudaGetSymbolAddress((void**)&p_We, g_We);
    cudaGetSymbolAddress((void**)&p_Wp, g_Wp);

    cudaFuncSetAttribute(gemm_k<N1, false>, cudaFuncAttributeMaxDynamicSharedMemorySize, SMEM_SZ);
    cudaFuncSetAttribute(gemm_k<KD, true >, cudaFuncAttributeMaxDynamicSharedMemorySize, SMEM_SZ);

    {
        size_t n4 = (size_t)N1 * KD / 4;
        round_We_k<<<(unsigned)((n4 + 255) / 256), 256>>>(We);
        n4 = (size_t)KD * KD / 4;
        round_Wp_k<<<(unsigned)((n4 + 255) / 256), 256>>>(Wp);
    }

    rmsnorm_k<<<MTOT, 256>>>(x);

    // h = xn @ We^T   [16384 x 6144]
    gemm_k<N1, false><<<dim3(N1 / BN, MTOT / BM), 256, SMEM_SZ>>>(p_xn, p_We, p_h, nullptr, nullptr);

    {
        size_t n = (size_t)MTOT * DIMD;
        gateconv_k<<<(unsigned)((n + 255) / 256), 256>>>(cw, cb, dil);
    }

    // out = x + cs * (o @ Wp^T)   [16384 x 2048]
    gemm_k<KD, true><<<dim3(KD / BN, MTOT / BM), 256, SMEM_SZ>>>(p_o, p_Wp, out, x, cs);
}

// round 4
// speedup vs baseline: 1.2441x; 1.1077x over previous
#include <cuda_runtime.h>
#include <cstdint>
#include <cstddef>

// ---------------- problem constants ----------------
#define DIMD   2048
#define MTOT   16384            // 4*4096 tokens
#define N1     6144             // 3*DIMD
#define KD     2048
#define SEQ    4096

// ---------------- scratch ----------------
__device__ float g_xn[(size_t)MTOT * KD];
__device__ float g_h [(size_t)MTOT * N1];
__device__ float g_o [(size_t)MTOT * KD];
__device__ float g_We[(size_t)N1  * KD];
__device__ float g_Wp[(size_t)KD  * KD];

// ---------------- helpers ----------------
__device__ __forceinline__ float to_tf32(float x) {
    float r; asm("cvt.rna.tf32.f32 %0, %1;" : "=f"(r) : "f"(x)); return r;
}
__device__ __forceinline__ void cpasync16(void* smem, const void* gmem) {
    uint32_t s = (uint32_t)__cvta_generic_to_shared(smem);
    asm volatile("cp.async.cg.shared.global [%0], [%1], 16;" :: "r"(s), "l"(gmem));
}
#define CP_COMMIT() asm volatile("cp.async.commit_group;")
#define CP_WAIT1()  asm volatile("cp.async.wait_group 1;")

__device__ __forceinline__ void mma_tf32(float c[4], const uint32_t a[4], const uint32_t b[2]) {
    asm volatile(
        "mma.sync.aligned.m16n8k8.row.col.f32.tf32.tf32.f32 "
        "{%0,%1,%2,%3}, {%4,%5,%6,%7}, {%8,%9}, {%0,%1,%2,%3};"
        : "+f"(c[0]), "+f"(c[1]), "+f"(c[2]), "+f"(c[3])
        : "r"(a[0]), "r"(a[1]), "r"(a[2]), "r"(a[3]),
          "r"(b[0]), "r"(b[1]));
}

// ---------------- tf32 GEMM v4: C[M,N] = A[M,K] * B[N,K]^T ----------------
// CTA 128x256, 8 warps (2M x 4N), warp tile 64x64.
// BK=32 (4 ks-steps of k8 per smem tile) -> one __syncthreads per 4 MMA
// batches. 3-stage cp.async pipeline + register ping-pong fragments.
constexpr int BM = 128, BN = 256, BK = 32, NSTG = 3;
constexpr int LDS_STRIDE = BK + 4;                   // 36 floats
constexpr int A_FLOATS = BM * LDS_STRIDE;            // 4608
constexpr int B_FLOATS = BN * LDS_STRIDE;            // 9216
constexpr int STG_FLOATS = A_FLOATS + B_FLOATS;      // 13824
constexpr int SMEM_SZ = NSTG * STG_FLOATS * 4;       // 165888 B

template<int N, bool FUSE>
__global__ void __launch_bounds__(256, 1) gemm_k(const float* __restrict__ A,
                                                 const float* __restrict__ B,
                                                 float* __restrict__ C,
                                                 const float* __restrict__ xres,
                                                 const float* __restrict__ cs) {
    constexpr int K = KD;
    constexpr int KT = K / BK;    // 64
    extern __shared__ float smem[];

    const int bm = blockIdx.y * BM;
    const int bn = blockIdx.x * BN;
    const int tid  = threadIdx.x;
    const int warp = tid >> 5, lane = tid & 31;
    const int wm = (warp & 1) * 64;
    const int wn = (warp >> 1) * 64;
    const int gid = lane >> 2, tig = lane & 3;

    float acc[4][8][4];
    #pragma unroll
    for (int mi = 0; mi < 4; mi++)
        #pragma unroll
        for (int ni = 0; ni < 8; ni++)
            #pragma unroll
            for (int r = 0; r < 4; r++) acc[mi][ni][r] = 0.f;

    const float* Abase = A + (size_t)bm * K;
    const float* Bbase = B + (size_t)bn * K;

    auto load_stage = [&](int kt) {
        float* sa = smem + (kt % NSTG) * STG_FLOATS;
        float* sb = sa + A_FLOATS;
        const float* Ag = Abase + kt * BK;
        const float* Bg = Bbase + kt * BK;
        // A: 128 rows x 8 chunks(16B) = 1024, 4 per thread
        #pragma unroll
        for (int i = 0; i < 4; i++) {
            int c = tid + i * 256;
            int row = c >> 3, ck = c & 7;
            cpasync16(sa + row * LDS_STRIDE + ck * 4, Ag + (size_t)row * K + ck * 4);
        }
        // B: 256 rows x 8 chunks = 2048, 8 per thread
        #pragma unroll
        for (int i = 0; i < 8; i++) {
            int c = tid + i * 256;
            int row = c >> 3, ck = c & 7;
            cpasync16(sb + row * LDS_STRIDE + ck * 4, Bg + (size_t)row * K + ck * 4);
        }
    };

    uint32_t fa[2][4][4];
    uint32_t fb[2][8][2];

    auto load_frags = [&](int buf, int stage, int ks) {
        const float* sa = smem + stage * STG_FLOATS;
        const float* sb = sa + A_FLOATS;
        const int k0 = ks * 8;
        #pragma unroll
        for (int mi = 0; mi < 4; mi++) {
            const float* p = sa + (wm + mi * 16 + gid) * LDS_STRIDE + k0;
            fa[buf][mi][0] = __float_as_uint(p[tig]);
            fa[buf][mi][1] = __float_as_uint(p[8 * LDS_STRIDE + tig]);
            fa[buf][mi][2] = __float_as_uint(p[tig + 4]);
            fa[buf][mi][3] = __float_as_uint(p[8 * LDS_STRIDE + tig + 4]);
        }
        #pragma unroll
        for (int ni = 0; ni < 8; ni++) {
            const float* p = sb + (wn + ni * 8 + gid) * LDS_STRIDE + k0;
            fb[buf][ni][0] = __float_as_uint(p[tig]);
            fb[buf][ni][1] = __float_as_uint(p[tig + 4]);
        }
    };

    auto mma_all = [&](int buf) {
        #pragma unroll
        for (int mi = 0; mi < 4; mi++)
            #pragma unroll
            for (int ni = 0; ni < 8; ni++)
                mma_tf32(acc[mi][ni], fa[buf][mi], fb[buf][ni]);
    };

    // prologue: 2 stages in flight
    load_stage(0); CP_COMMIT();
    load_stage(1); CP_COMMIT();
    CP_WAIT1();
    __syncthreads();
    load_frags(0, 0, 0);

    #pragma unroll 1
    for (int kt = 0; kt < KT; kt++) {
        const int stage = kt % NSTG;

        // ks0 (buf0 preloaded)
        load_frags(1, stage, 1);
        if (kt + 2 < KT) load_stage(kt + 2);
        CP_COMMIT();
        mma_all(0);
        // ks1
        load_frags(0, stage, 2);
        mma_all(1);
        // ks2
        load_frags(1, stage, 3);
        mma_all(0);
        // ks3
        if (kt + 1 < KT) {
            CP_WAIT1();
            __syncthreads();
            load_frags(0, (kt + 1) % NSTG, 0);
        }
        mma_all(1);
    }

    // epilogue
    #pragma unroll
    for (int mi = 0; mi < 4; mi++) {
        #pragma unroll
        for (int ni = 0; ni < 8; ni++) {
            int r0 = bm + wm + mi * 16 + gid;
            int c0 = bn + wn + ni * 8 + tig * 2;
            #pragma unroll
            for (int h = 0; h < 2; h++) {
                int r = r0 + h * 8;
                size_t off = (size_t)r * N + c0;
                float v0 = acc[mi][ni][2 * h + 0];
                float v1 = acc[mi][ni][2 * h + 1];
                if (FUSE) {
                    v0 = xres[off]     + cs[c0]     * v0;
                    v1 = xres[off + 1] + cs[c0 + 1] * v1;
                }
                float2 st; st.x = v0; st.y = v1;
                *(float2*)(C + off) = st;
            }
        }
    }
}

// ---------------- prep: round weights to tf32 (RNA) ----------------
__global__ void round_We_k(const float* __restrict__ src) {
    size_t i = (size_t)blockIdx.x * blockDim.x + threadIdx.x;
    size_t n4 = (size_t)N1 * KD / 4;
    if (i >= n4) return;
    float4 v = ((const float4*)src)[i];
    v.x = to_tf32(v.x); v.y = to_tf32(v.y); v.z = to_tf32(v.z); v.w = to_tf32(v.w);
    ((float4*)g_We)[i] = v;
}
__global__ void round_Wp_k(const float* __restrict__ src) {
    size_t i = (size_t)blockIdx.x * blockDim.x + threadIdx.x;
    size_t n4 = (size_t)KD * KD / 4;
    if (i >= n4) return;
    float4 v = ((const float4*)src)[i];
    v.x = to_tf32(v.x); v.y = to_tf32(v.y); v.z = to_tf32(v.z); v.w = to_tf32(v.w);
    ((float4*)g_Wp)[i] = v;
}

// ---------------- rmsnorm ----------------
__global__ void __launch_bounds__(256) rmsnorm_k(const float* __restrict__ x) {
    int row = blockIdx.x;
    const float4* xr = (const float4*)(x + (size_t)row * DIMD);
    float4* outr = (float4*)(g_xn + (size_t)row * DIMD);
    int t = threadIdx.x;

    float4 a = xr[t];
    float4 b = xr[t + 256];
    float ss = a.x*a.x + a.y*a.y + a.z*a.z + a.w*a.w
             + b.x*b.x + b.y*b.y + b.z*b.z + b.w*b.w;
    #pragma unroll
    for (int off = 16; off > 0; off >>= 1)
        ss += __shfl_xor_sync(0xffffffffu, ss, off);

    __shared__ float red[8];
    __shared__ float sscale;
    int warp = t >> 5, lane = t & 31;
    if (lane == 0) red[warp] = ss;
    __syncthreads();
    if (t == 0) {
        float tot = 0.f;
        #pragma unroll
        for (int i = 0; i < 8; i++) tot += red[i];
        sscale = rsqrtf(tot * (1.0f / DIMD) + 1.1920928955078125e-07f);
    }
    __syncthreads();
    float sc = sscale;
    a.x = to_tf32(a.x * sc); a.y = to_tf32(a.y * sc); a.z = to_tf32(a.z * sc); a.w = to_tf32(a.w * sc);
    b.x = to_tf32(b.x * sc); b.y = to_tf32(b.y * sc); b.z = to_tf32(b.z * sc); b.w = to_tf32(b.w * sc);
    outr[t] = a;
    outr[t + 256] = b;
}

// ---------------- gate * causal dwconv * gate ----------------
__global__ void __launch_bounds__(256) gateconv_k(const float* __restrict__ cw,
                                                  const float* __restrict__ cb,
                                                  const int* __restrict__ dil_p) {
    int dil = *dil_p;
    size_t idx = (size_t)blockIdx.x * blockDim.x + threadIdx.x;
    if (idx >= (size_t)MTOT * DIMD) return;
    int d = (int)(idx % DIMD);
    int m = (int)(idx / DIMD);
    int s = m % SEQ;

    const float* hr = g_h + (size_t)m * N1;
    float w0 = cw[d * 3 + 0], w1 = cw[d * 3 + 1], w2 = cw[d * 3 + 2];

    float acc = cb[d];
    acc += w2 * (hr[d] * hr[2 * DIMD + d]);
    if (s >= dil) {
        const float* hp = hr - (size_t)dil * N1;
        acc += w1 * (hp[d] * hp[2 * DIMD + d]);
    }
    if (s >= 2 * dil) {
        const float* hp = hr - (size_t)(2 * dil) * N1;
        acc += w0 * (hp[d] * hp[2 * DIMD + d]);
    }
    float Cg = hr[DIMD + d];
    g_o[idx] = to_tf32(Cg * acc);
}

// ---------------- launch ----------------
extern "C" void kernel_launch(void* const* d_in, const int* in_sizes, int n_in,
                              void* d_out, int out_size) {
    const float* x   = (const float*)d_in[0];
    const float* We  = (const float*)d_in[1];
    const float* cw  = (const float*)d_in[2];
    const float* cb  = (const float*)d_in[3];
    const float* Wp  = (const float*)d_in[4];
    const float* cs  = (const float*)d_in[5];
    const int*   dil = (const int*)  d_in[6];
    float* out = (float*)d_out;

    float *p_xn, *p_h, *p_o, *p_We, *p_Wp;
    cudaGetSymbolAddress((void**)&p_xn, g_xn);
    cudaGetSymbolAddress((void**)&p_h,  g_h);
    cudaGetSymbolAddress((void**)&p_o,  g_o);
    cudaGetSymbolAddress((void**)&p_We, g_We);
    cudaGetSymbolAddress((void**)&p_Wp, g_Wp);

    cudaFuncSetAttribute(gemm_k<N1, false>, cudaFuncAttributeMaxDynamicSharedMemorySize, SMEM_SZ);
    cudaFuncSetAttribute(gemm_k<KD, true >, cudaFuncAttributeMaxDynamicSharedMemorySize, SMEM_SZ);

    {
        size_t n4 = (size_t)N1 * KD / 4;
        round_We_k<<<(unsigned)((n4 + 255) / 256), 256>>>(We);
        n4 = (size_t)KD * KD / 4;
        round_Wp_k<<<(unsigned)((n4 + 255) / 256), 256>>>(Wp);
    }

    rmsnorm_k<<<MTOT, 256>>>(x);

    // h = xn @ We^T   [16384 x 6144]
    gemm_k<N1, false><<<dim3(N1 / BN, MTOT / BM), 256, SMEM_SZ>>>(p_xn, p_We, p_h, nullptr, nullptr);

    {
        size_t n = (size_t)MTOT * DIMD;
        gateconv_k<<<(unsigned)((n + 255) / 256), 256>>>(cw, cb, dil);
    }

    // out = x + cs * (o @ Wp^T)   [16384 x 2048]
    gemm_k<KD, true><<<dim3(KD / BN, MTOT / BM), 256, SMEM_SZ>>>(p_o, p_Wp, out, x, cs);
}